// round 12
// baseline (speedup 1.0000x reference)
#include <cuda_runtime.h>
#include <cuda_bf16.h>

// 2-layer GCN:
//   per layer: xw = X@W ; agg = segment_sum(xw[src] -> dst) ;
//              h = relu(agg + b) + relu(X@Wr + br)
//
// N = 100000 nodes, E = 1200000 edges, D = 64.
//
// Launch plan (default stream, graph-capturable, allocation-free):
//   L1: gemm<MODE0>(feats,W1)  -> g_xw, zero g_agg
//       scatter(src,dst)       -> g_agg += g_xw[src]  (red.global.add.v4.f32)
//       gemm<MODE1>(feats,Wr1) -> g_h1 = relu(g_agg+b1) + relu(feats@Wr1+br1)
//   L2: same with g_h1 as input, final output to d_out.

static constexpr int NN = 100000;
static constexpr int EE = 1200000;
static constexpr int DD = 64;

// Scratch (device globals; no runtime allocation). 16B-aligned for float4/red.v4.
__device__ __align__(16) float g_xw [NN * DD];
__device__ __align__(16) float g_agg[NN * DD];
__device__ __align__(16) float g_h1 [NN * DD];

// XOR-swizzled transposed X tile index:
// logical element (k, r) of XsT[64][64] stored at
//   k*64 + ( ((r>>2) ^ ((k>>2)&15)) * 4 + (r&3) )
// -> transpose stores are ~2-way bank conflicted, compute reads are
//    broadcast LDS.128 (all lanes in a warp read the same float4).
__device__ __forceinline__ int swidx(int k, int r) {
    return (k << 6) + (((((r >> 2) ^ ((k >> 2) & 15))) << 2) | (r & 3));
}

// MODE 0: Y(=g_xw) = X @ W ; also zero g_agg rows (so scatter can accumulate).
// MODE 1: Y = relu(X @ W + bias_r) + relu(g_agg + bias_a)   (fused epilogue)
// XH1: read X from g_h1 instead of param. YH1: write Y to g_h1 instead of param.
template<int MODE, bool XH1, bool YH1>
__global__ __launch_bounds__(256)
void gemm64_k(const float* __restrict__ Xp,
              const float* __restrict__ W,
              const float* __restrict__ bias_r,
              const float* __restrict__ bias_a,
              float* __restrict__ Yp,
              int n)
{
    __shared__ float XsT[64 * 64];   // 16 KB, transposed + swizzled
    __shared__ float Ws [64 * 64];   // 16 KB, row-major: Ws[k*64 + j]

    const float* X = XH1 ? (const float*)g_h1 : Xp;
    float*       Y = YH1 ? (float*)g_h1       : Yp;

    const int tid  = threadIdx.x;
    const int row0 = blockIdx.x << 6;

    // Stage W (4096 floats = 1024 float4, 256 threads x 4)
    const float4* W4 = (const float4*)W;
    float4* Ws4 = (float4*)Ws;
#pragma unroll
    for (int i = 0; i < 4; ++i) Ws4[tid + i * 256] = W4[tid + i * 256];

    // Stage X tile transposed+swizzled. Each thread: 4 float4 loads.
    const float4* X4 = (const float4*)X;
#pragma unroll
    for (int i = 0; i < 4; ++i) {
        int idx = tid + i * 256;          // 0..1023
        int r   = idx >> 4;               // tile row 0..63
        int c4  = idx & 15;               // float4 column 0..15
        int row = row0 + r;
        float4 v = make_float4(0.f, 0.f, 0.f, 0.f);
        if (row < n) v = X4[row * 16 + c4];
        int c = c4 << 2;
        XsT[swidx(c + 0, r)] = v.x;
        XsT[swidx(c + 1, r)] = v.y;
        XsT[swidx(c + 2, r)] = v.z;
        XsT[swidx(c + 3, r)] = v.w;
    }
    __syncthreads();

    // Each thread: output column j, 16 rows (rg*16 .. rg*16+15).
    const int j  = tid & 63;
    const int rg = tid >> 6;              // 0..3

    float acc[16];
#pragma unroll
    for (int m = 0; m < 16; ++m) acc[m] = 0.f;

#pragma unroll 8
    for (int k = 0; k < 64; ++k) {
        float wv = Ws[(k << 6) + j];
        const float4* xk = (const float4*)(XsT + (k << 6));
        int sw = (k >> 2) & 15;
        float4 a0 = xk[((rg << 2) + 0) ^ sw];   // rows rg*16 + 0..3
        float4 a1 = xk[((rg << 2) + 1) ^ sw];   // rows rg*16 + 4..7
        float4 a2 = xk[((rg << 2) + 2) ^ sw];   // rows rg*16 + 8..11
        float4 a3 = xk[((rg << 2) + 3) ^ sw];   // rows rg*16 + 12..15
        acc[ 0] += a0.x * wv;  acc[ 1] += a0.y * wv;
        acc[ 2] += a0.z * wv;  acc[ 3] += a0.w * wv;
        acc[ 4] += a1.x * wv;  acc[ 5] += a1.y * wv;
        acc[ 6] += a1.z * wv;  acc[ 7] += a1.w * wv;
        acc[ 8] += a2.x * wv;  acc[ 9] += a2.y * wv;
        acc[10] += a2.z * wv;  acc[11] += a2.w * wv;
        acc[12] += a3.x * wv;  acc[13] += a3.y * wv;
        acc[14] += a3.z * wv;  acc[15] += a3.w * wv;
    }

    const int rbase = row0 + (rg << 4);
    if (MODE == 0) {
#pragma unroll
        for (int m = 0; m < 16; ++m) {
            int row = rbase + m;
            if (row < n) {
                g_xw [row * 64 + j] = acc[m];
                g_agg[row * 64 + j] = 0.f;     // pre-zero for scatter
            }
        }
    } else {
        float brj = bias_r[j];
        float baj = bias_a[j];
#pragma unroll
        for (int m = 0; m < 16; ++m) {
            int row = rbase + m;
            if (row < n) {
                float conv = g_agg[row * 64 + j] + baj;
                conv = conv > 0.f ? conv : 0.f;
                float res = acc[m] + brj;
                res = res > 0.f ? res : 0.f;
                Y[row * 64 + j] = conv + res;
            }
        }
    }
}

// Vectorized 16B float atomic add (sm_90+): 4 fp32 adds per L2 atomic op.
__device__ __forceinline__ void red_add_v4(float4* addr, float4 v) {
    asm volatile("red.global.add.v4.f32 [%0], {%1, %2, %3, %4};"
                 :: "l"(addr), "f"(v.x), "f"(v.y), "f"(v.z), "f"(v.w)
                 : "memory");
}

// One thread per (edge, float4-quad): 16 threads per edge, fully coalesced
// 256B gather per edge, 16B vector red per thread.
__global__ __launch_bounds__(256)
void scatter_k(const int* __restrict__ src, const int* __restrict__ dst)
{
    unsigned gid = blockIdx.x * 256u + threadIdx.x;   // EE*16 = 19.2M exact
    unsigned e = gid >> 4;
    unsigned q = gid & 15;
    int s = __ldg(src + e);
    int d = __ldg(dst + e);
    const float4* xw4 = (const float4*)g_xw;
    float4 v = __ldg(xw4 + (size_t)s * 16 + q);
    red_add_v4(((float4*)g_agg) + (size_t)d * 16 + q, v);
}

extern "C" void kernel_launch(void* const* d_in, const int* in_sizes, int n_in,
                              void* d_out, int out_size)
{
    const float* feats = (const float*)d_in[0];
    const float* W1    = (const float*)d_in[1];
    const float* b1    = (const float*)d_in[2];
    const float* Wr1   = (const float*)d_in[3];
    const float* br1   = (const float*)d_in[4];
    const float* W2    = (const float*)d_in[5];
    const float* b2    = (const float*)d_in[6];
    const float* Wr2   = (const float*)d_in[7];
    const float* br2   = (const float*)d_in[8];
    const int*   src   = (const int*)d_in[9];
    const int*   dst   = (const int*)d_in[10];
    float*       out   = (float*)d_out;

    const int GB = (NN + 63) >> 6;            // 1563 blocks
    const int SB = (EE * 16) / 256;           // 75000 blocks

    // ---- Layer 1 ----
    gemm64_k<0, false, false><<<GB, 256>>>(feats, W1, nullptr, nullptr, nullptr, NN);
    scatter_k<<<SB, 256>>>(src, dst);
    gemm64_k<1, false, true ><<<GB, 256>>>(feats, Wr1, br1, b1, nullptr, NN);

    // ---- Layer 2 ----
    gemm64_k<0, true,  false><<<GB, 256>>>(nullptr, W2, nullptr, nullptr, nullptr, NN);
    scatter_k<<<SB, 256>>>(src, dst);
    gemm64_k<1, true,  false><<<GB, 256>>>(nullptr, Wr2, br2, b2, out, NN);
}